// round 1
// baseline (speedup 1.0000x reference)
#include <cuda_runtime.h>
#include <cuda_bf16.h>
#include <cstdint>

#define N_TOK 8192
#define DIM   64
#define BM    64
#define BN    128
#define NITER (N_TOK / BN)

// Scratch for projected Q (pre-scaled by 1/8) and K
__device__ float g_Q[N_TOK * DIM];
__device__ float g_K[N_TOK * DIM];

// ---------- f32x2 helpers (Blackwell packed fp32 pipe) ----------
__device__ __forceinline__ unsigned long long pk2(float a, float b) {
    unsigned long long r;
    asm("mov.b64 %0, {%1, %2};" : "=l"(r) : "f"(a), "f"(b));
    return r;
}
__device__ __forceinline__ void upk2(unsigned long long v, float& a, float& b) {
    asm("mov.b64 {%0, %1}, %2;" : "=f"(a), "=f"(b) : "l"(v));
}
__device__ __forceinline__ unsigned long long fma2(unsigned long long a,
                                                   unsigned long long b,
                                                   unsigned long long c) {
    unsigned long long d;
    asm("fma.rn.f32x2 %0, %1, %2, %3;" : "=l"(d) : "l"(a), "l"(b), "l"(c));
    return d;
}
__device__ __forceinline__ unsigned long long mul2(unsigned long long a,
                                                   unsigned long long b) {
    unsigned long long d;
    asm("mul.rn.f32x2 %0, %1, %2;" : "=l"(d) : "l"(a), "l"(b));
    return d;
}

// ---------- projection: Q = (x @ R) * 0.125, K = x @ E ----------
__global__ __launch_bounds__(256, 4) void proj_kernel(const float* __restrict__ x,
                                                      const float* __restrict__ R,
                                                      const float* __restrict__ E) {
    __shared__ float Rs[64 * 64];
    __shared__ float Es[64 * 64];
    __shared__ float xs[4][64];
    int tid = threadIdx.x;
    // load R, E (4096 floats each)
    {
        const float4* Rsrc = (const float4*)R;
        const float4* Esrc = (const float4*)E;
        float4* Rd = (float4*)Rs;
        float4* Ed = (float4*)Es;
#pragma unroll
        for (int i = tid; i < 1024; i += 256) {
            Rd[i] = Rsrc[i];
            Ed[i] = Esrc[i];
        }
    }
    int ty  = tid >> 6;          // 0..3
    int col = tid & 63;          // 0..63
    int row = blockIdx.x * 4 + ty;
    xs[ty][col] = x[row * 64 + col];
    __syncthreads();

    float aq = 0.f, ak = 0.f;
#pragma unroll 16
    for (int k = 0; k < 64; k++) {
        float xv = xs[ty][k];
        aq = fmaf(xv, Rs[k * 64 + col], aq);
        ak = fmaf(xv, Es[k * 64 + col], ak);
    }
    g_Q[row * 64 + col] = aq * 0.125f;   // fold 1/sqrt(64) into Q
    g_K[row * 64 + col] = ak;
}

// ---------- flash attention, fp32 via packed f32x2 ----------
// smem layout (floats): Qs[64*64] | Ks[128*64] (xor-swizzled) | Xs[128*64] | Ps[64*128]
#define SMEM_FLOATS (4096 + 8192 + 8192 + 8192)
#define SMEM_BYTES  (SMEM_FLOATS * 4)

__global__ __launch_bounds__(256, 1) void attn_kernel(const float* __restrict__ x,
                                                      float* __restrict__ out) {
    extern __shared__ float sm[];
    float* Qs = sm;             // [m][k]  natural
    float* Ks = sm + 4096;      // [n][k]  chunk-swizzled: chunk' = kc ^ ((n>>3)&7)
    float* Xs = sm + 12288;     // [j][c]  natural
    float* Ps = sm + 20480;     // [m][j]  natural

    int tid = threadIdx.x;
    int tx = tid & 15;          // 0..15
    int ty = tid >> 4;          // 0..15
    int r0 = ty * 4;            // 4 rows owned
    int n0 = tx * 8;            // 8 key-cols owned (GEMM1)
    int c0 = tx * 4;            // 4 d-cols owned (GEMM2)
    int rowbase = blockIdx.x * BM;

    // load Q tile once
    {
        const float4* src = (const float4*)(g_Q + (size_t)rowbase * DIM);
        float4* dst = (float4*)Qs;
#pragma unroll
        for (int i = tid; i < BM * 16; i += 256) dst[i] = src[i];
    }

    unsigned long long o2[4][4];   // O accumulator, even/odd-j partial sums packed
    float mrow[4], lrow[4];
#pragma unroll
    for (int i = 0; i < 4; i++) {
        mrow[i] = -3.0e38f;
        lrow[i] = 0.f;
#pragma unroll
        for (int c = 0; c < 4; c++) o2[i][c] = 0ull;
    }

    for (int it = 0; it < NITER; it++) {
        __syncthreads();   // all warps done reading Ks/Xs/Ps of previous iter
        // ---- load K (swizzled) and X tiles ----
        {
            int kb = it * BN;
            const float4* Ksrc = (const float4*)(g_K + (size_t)kb * DIM);
            const float4* Xsrc = (const float4*)(x + (size_t)kb * DIM);
            float4* Kd = (float4*)Ks;
            float4* Xd = (float4*)Xs;
#pragma unroll
            for (int i = tid; i < BN * 16; i += 256) {
                int n = i >> 4;
                int kc = i & 15;
                int cs = kc ^ ((n >> 3) & 7);
                Kd[n * 16 + cs] = Ksrc[i];
                Xd[i] = Xsrc[i];
            }
        }
        __syncthreads();

        // ---- GEMM1: S = Q @ K^T  (even/odd-k partials in f32x2 lanes) ----
        unsigned long long s2[4][8];
#pragma unroll
        for (int i = 0; i < 4; i++)
#pragma unroll
            for (int j = 0; j < 8; j++) s2[i][j] = 0ull;

#pragma unroll 4
        for (int kc = 0; kc < 16; kc++) {
            ulonglong2 qv[4];
#pragma unroll
            for (int i = 0; i < 4; i++)
                qv[i] = *(const ulonglong2*)(Qs + (r0 + i) * 64 + kc * 4);
#pragma unroll
            for (int j = 0; j < 8; j++) {
                int n = n0 + j;
                int cs = kc ^ ((n >> 3) & 7);
                ulonglong2 kv = *(const ulonglong2*)(Ks + n * 64 + cs * 4);
#pragma unroll
                for (int i = 0; i < 4; i++) {
                    s2[i][j] = fma2(qv[i].x, kv.x, s2[i][j]);
                    s2[i][j] = fma2(qv[i].y, kv.y, s2[i][j]);
                }
            }
        }

        // ---- online softmax on S ----
        float s[4][8];
#pragma unroll
        for (int i = 0; i < 4; i++)
#pragma unroll
            for (int j = 0; j < 8; j++) {
                float lo, hi;
                upk2(s2[i][j], lo, hi);
                s[i][j] = lo + hi;
            }

        float scl[4];
#pragma unroll
        for (int i = 0; i < 4; i++) {
            float rm = s[i][0];
#pragma unroll
            for (int j = 1; j < 8; j++) rm = fmaxf(rm, s[i][j]);
#pragma unroll
            for (int d = 8; d >= 1; d >>= 1)
                rm = fmaxf(rm, __shfl_xor_sync(0xffffffffu, rm, d));
            float mn = fmaxf(mrow[i], rm);
            float sc = __expf(mrow[i] - mn);
            mrow[i] = mn;
            float rs = 0.f;
#pragma unroll
            for (int j = 0; j < 8; j++) {
                float p = __expf(s[i][j] - mn);
                s[i][j] = p;
                rs += p;
            }
#pragma unroll
            for (int d = 8; d >= 1; d >>= 1)
                rs += __shfl_xor_sync(0xffffffffu, rs, d);
            lrow[i] = lrow[i] * sc + rs;
            scl[i] = sc;
        }

        // ---- stash P (rows are produced & consumed within one warp) ----
#pragma unroll
        for (int i = 0; i < 4; i++) {
            *(float4*)(Ps + (r0 + i) * BN + n0) =
                make_float4(s[i][0], s[i][1], s[i][2], s[i][3]);
            *(float4*)(Ps + (r0 + i) * BN + n0 + 4) =
                make_float4(s[i][4], s[i][5], s[i][6], s[i][7]);
        }
        __syncwarp();

        // ---- rescale O, then GEMM2: O += P @ X (even/odd-j partials) ----
#pragma unroll
        for (int i = 0; i < 4; i++) {
            unsigned long long scp = pk2(scl[i], scl[i]);
#pragma unroll
            for (int c = 0; c < 4; c++) o2[i][c] = mul2(o2[i][c], scp);
        }

#pragma unroll 8
        for (int j = 0; j < BN; j += 2) {
            unsigned long long pd[4];
#pragma unroll
            for (int i = 0; i < 4; i++)
                pd[i] = *(const unsigned long long*)(Ps + (r0 + i) * BN + j);
            float4 xa = *(const float4*)(Xs + j * 64 + c0);
            float4 xb = *(const float4*)(Xs + (j + 1) * 64 + c0);
            unsigned long long xq0 = pk2(xa.x, xb.x);
            unsigned long long xq1 = pk2(xa.y, xb.y);
            unsigned long long xq2 = pk2(xa.z, xb.z);
            unsigned long long xq3 = pk2(xa.w, xb.w);
#pragma unroll
            for (int i = 0; i < 4; i++) {
                o2[i][0] = fma2(pd[i], xq0, o2[i][0]);
                o2[i][1] = fma2(pd[i], xq1, o2[i][1]);
                o2[i][2] = fma2(pd[i], xq2, o2[i][2]);
                o2[i][3] = fma2(pd[i], xq3, o2[i][3]);
            }
        }
    }

    // ---- epilogue: O / l ----
#pragma unroll
    for (int i = 0; i < 4; i++) {
        float inv = 1.0f / lrow[i];
        float a, b;
        float4 o;
        upk2(o2[i][0], a, b); o.x = (a + b) * inv;
        upk2(o2[i][1], a, b); o.y = (a + b) * inv;
        upk2(o2[i][2], a, b); o.z = (a + b) * inv;
        upk2(o2[i][3], a, b); o.w = (a + b) * inv;
        *(float4*)(out + (size_t)(rowbase + r0 + i) * 64 + c0) = o;
    }
}

extern "C" void kernel_launch(void* const* d_in, const int* in_sizes, int n_in,
                              void* d_out, int out_size) {
    const float* x = (const float*)d_in[0];
    const float* R = (const float*)d_in[1];
    const float* E = (const float*)d_in[2];
    float* out = (float*)d_out;

    proj_kernel<<<N_TOK / 4, 256>>>(x, R, E);

    cudaFuncSetAttribute(attn_kernel, cudaFuncAttributeMaxDynamicSharedMemorySize,
                         SMEM_BYTES);
    attn_kernel<<<N_TOK / BM, 256, SMEM_BYTES>>>(x, out);
}

// round 4
// speedup vs baseline: 2.9280x; 2.9280x over previous
#include <cuda_runtime.h>
#include <cuda_bf16.h>
#include <cstdint>

#define N_TOK 8192
#define DIM   64
#define BM    128
#define BN    128
#define HALF_KV 4096
#define NITER (HALF_KV / BN)   // 32

// ---------------- global scratch ----------------
__device__ __nv_bfloat16 g_Qh[N_TOK * DIM], g_Ql[N_TOK * DIM];
__device__ __nv_bfloat16 g_Kh[N_TOK * DIM], g_Kl[N_TOK * DIM];
__device__ __nv_bfloat16 g_Xth[DIM * N_TOK], g_Xtl[DIM * N_TOK];
__device__ float g_Opart[2][N_TOK * DIM];
__device__ float g_mpart[2][N_TOK];
__device__ float g_lpart[2][N_TOK];

// ---------------- helpers ----------------
__device__ __forceinline__ uint32_t smem_u32(const void* p) {
    uint32_t a;
    asm("{ .reg .u64 t; cvta.to.shared.u64 t, %1; cvt.u32.u64 %0, t; }" : "=r"(a) : "l"(p));
    return a;
}
// 128B rows (8 chunks of 16B): XOR-swizzle chunk by row&7
__device__ __forceinline__ uint32_t swz8(uint32_t row, uint32_t ch) {
    return row * 128u + ((ch ^ (row & 7u)) << 4);
}
// 256B rows (16 chunks): XOR affects low 3 bits of chunk only
__device__ __forceinline__ uint32_t swz16(uint32_t row, uint32_t ch) {
    return row * 256u + ((ch ^ (row & 7u)) << 4);
}
__device__ __forceinline__ void ldsm4(uint32_t& r0, uint32_t& r1, uint32_t& r2,
                                      uint32_t& r3, uint32_t addr) {
    asm volatile("ldmatrix.sync.aligned.m8n8.x4.shared.b16 {%0,%1,%2,%3}, [%4];"
                 : "=r"(r0), "=r"(r1), "=r"(r2), "=r"(r3) : "r"(addr));
}
__device__ __forceinline__ void mma16816(float* c, const uint32_t* a, uint32_t b0,
                                         uint32_t b1) {
    asm volatile(
        "mma.sync.aligned.m16n8k16.row.col.f32.bf16.bf16.f32 "
        "{%0,%1,%2,%3}, {%4,%5,%6,%7}, {%8,%9}, {%0,%1,%2,%3};"
        : "+f"(c[0]), "+f"(c[1]), "+f"(c[2]), "+f"(c[3])
        : "r"(a[0]), "r"(a[1]), "r"(a[2]), "r"(a[3]), "r"(b0), "r"(b1));
}
__device__ __forceinline__ uint32_t pk2bf(float a, float b) {
    __nv_bfloat16 ha = __float2bfloat16(a), hb = __float2bfloat16(b);
    return ((uint32_t)__bfloat16_as_ushort(hb) << 16) | (uint32_t)__bfloat16_as_ushort(ha);
}
// split pair into bf16-hi pack and bf16-lo (residual) pack
__device__ __forceinline__ void split2(float a, float b, uint32_t& hi, uint32_t& lo) {
    __nv_bfloat16 ha = __float2bfloat16(a), hb = __float2bfloat16(b);
    hi = ((uint32_t)__bfloat16_as_ushort(hb) << 16) | (uint32_t)__bfloat16_as_ushort(ha);
    lo = pk2bf(a - __bfloat162float(ha), b - __bfloat162float(hb));
}

// ---------------- projection + split kernel ----------------
__global__ __launch_bounds__(256, 4) void proj_kernel(const float* __restrict__ x,
                                                      const float* __restrict__ R,
                                                      const float* __restrict__ E) {
    __shared__ float Rs[64 * 64];
    __shared__ float Es[64 * 64];
    __shared__ float xs[4][64];
    int tid = threadIdx.x;
    {
        const float4* Rsrc = (const float4*)R;
        const float4* Esrc = (const float4*)E;
        float4* Rd = (float4*)Rs;
        float4* Ed = (float4*)Es;
#pragma unroll
        for (int i = tid; i < 1024; i += 256) { Rd[i] = Rsrc[i]; Ed[i] = Esrc[i]; }
    }
    int ty = tid >> 6, col = tid & 63;
    int row = blockIdx.x * 4 + ty;
    float xv0 = x[row * 64 + col];
    xs[ty][col] = xv0;
    __syncthreads();

    float aq = 0.f, ak = 0.f;
#pragma unroll 16
    for (int k = 0; k < 64; k++) {
        float xv = xs[ty][k];
        aq = fmaf(xv, Rs[k * 64 + col], aq);
        ak = fmaf(xv, Es[k * 64 + col], ak);
    }
    aq *= 0.125f;   // fold 1/sqrt(64)

    __nv_bfloat16 qh = __float2bfloat16(aq);
    __nv_bfloat16 ql = __float2bfloat16(aq - __bfloat162float(qh));
    __nv_bfloat16 kh = __float2bfloat16(ak);
    __nv_bfloat16 kl = __float2bfloat16(ak - __bfloat162float(kh));
    g_Qh[row * 64 + col] = qh;  g_Ql[row * 64 + col] = ql;
    g_Kh[row * 64 + col] = kh;  g_Kl[row * 64 + col] = kl;

    __nv_bfloat16 xh = __float2bfloat16(xv0);
    __nv_bfloat16 xl = __float2bfloat16(xv0 - __bfloat162float(xh));
    g_Xth[col * N_TOK + row] = xh;
    g_Xtl[col * N_TOK + row] = xl;
}

// ---------------- fused flash attention (mma.sync HMMA) ----------------
// smem (bytes): KH[16384] KL[16384] XH[16384] XL[16384]
#define OFF_KH 0
#define OFF_KL 16384
#define OFF_XH 32768
#define OFF_XL 49152
#define SMEM_TOTAL 65536

__global__ __launch_bounds__(256, 1) void attn_kernel() {
    extern __shared__ char sm[];
    uint32_t sb = smem_u32(sm);
    const int tid = threadIdx.x;
    const int lane = tid & 31;
    const int w = tid >> 5;
    const int m0 = w * 16;                  // warp's row base inside tile
    const int rb = blockIdx.x >> 1;
    const int half = blockIdx.x & 1;
    const int row0 = rb * BM;

    // ---- stage Q (hi/lo) into K smem region, build A-fragments once ----
#pragma unroll
    for (int i = tid; i < 128 * 8; i += 256) {
        int row = i >> 3, ch = i & 7;
        uint32_t sw = swz8(row, ch);
        *(uint4*)(sm + OFF_KH + sw) = *(const uint4*)(g_Qh + (size_t)(row0 + row) * DIM + ch * 8);
        *(uint4*)(sm + OFF_KL + sw) = *(const uint4*)(g_Ql + (size_t)(row0 + row) * DIM + ch * 8);
    }
    __syncthreads();

    uint32_t qh[4][4], ql[4][4];
    {
        int g = lane >> 3, rr = lane & 7;
        int arow = m0 + ((g & 1) << 3) + rr;
#pragma unroll
        for (int ks = 0; ks < 4; ks++) {
            uint32_t off = swz8(arow, ks * 2 + (g >> 1));
            ldsm4(qh[ks][0], qh[ks][1], qh[ks][2], qh[ks][3], sb + OFF_KH + off);
            ldsm4(ql[ks][0], ql[ks][1], ql[ks][2], ql[ks][3], sb + OFF_KL + off);
        }
    }

    float o[8][4];
#pragma unroll
    for (int t = 0; t < 8; t++)
#pragma unroll
        for (int j = 0; j < 4; j++) o[t][j] = 0.f;
    float mc0 = -3.0e38f, mc1 = -3.0e38f, lc0 = 0.f, lc1 = 0.f;

    for (int it = 0; it < NITER; it++) {
        __syncthreads();   // previous tiles fully consumed / Q frags done
        int jb = half * HALF_KV + it * BN;
        // ---- load K (hi/lo): 128 rows x 64 bf16, swizzled ----
#pragma unroll
        for (int i = tid; i < 128 * 8; i += 256) {
            int row = i >> 3, ch = i & 7;
            uint32_t sw = swz8(row, ch);
            *(uint4*)(sm + OFF_KH + sw) = *(const uint4*)(g_Kh + (size_t)(jb + row) * DIM + ch * 8);
            *(uint4*)(sm + OFF_KL + sw) = *(const uint4*)(g_Kl + (size_t)(jb + row) * DIM + ch * 8);
        }
        // ---- load Xt (hi/lo): 64 rows x 128 bf16 tokens, swizzled ----
#pragma unroll
        for (int i = tid; i < 64 * 16; i += 256) {
            int row = i >> 4, ch = i & 15;
            uint32_t sw = swz16(row, ch);
            *(uint4*)(sm + OFF_XH + sw) = *(const uint4*)(g_Xth + (size_t)row * N_TOK + jb + ch * 8);
            *(uint4*)(sm + OFF_XL + sw) = *(const uint4*)(g_Xtl + (size_t)row * N_TOK + jb + ch * 8);
        }
        __syncthreads();

        // ---- GEMM1: S = Qh*Kh + Qh*Kl + Ql*Kh ----
        float s[16][4];
#pragma unroll
        for (int t = 0; t < 16; t++)
#pragma unroll
            for (int j = 0; j < 4; j++) s[t][j] = 0.f;
        {
            int g = lane >> 3, rr = lane & 7;
#pragma unroll
            for (int np = 0; np < 8; np++) {
                int brow = np * 16 + ((g >> 1) << 3) + rr;
#pragma unroll
                for (int ks = 0; ks < 4; ks++) {
                    uint32_t off = swz8(brow, ks * 2 + (g & 1));
                    uint32_t b0, b1, b2, b3, c0, c1, c2, c3;
                    ldsm4(b0, b1, b2, b3, sb + OFF_KH + off);
                    ldsm4(c0, c1, c2, c3, sb + OFF_KL + off);
                    mma16816(s[2 * np],     qh[ks], b0, b1);
                    mma16816(s[2 * np + 1], qh[ks], b2, b3);
                    mma16816(s[2 * np],     qh[ks], c0, c1);
                    mma16816(s[2 * np + 1], qh[ks], c2, c3);
                    mma16816(s[2 * np],     ql[ks], b0, b1);
                    mma16816(s[2 * np + 1], ql[ks], b2, b3);
                }
            }
        }

        // ---- online softmax on C-fragments ----
        float mx0 = -3.0e38f, mx1 = -3.0e38f;
#pragma unroll
        for (int t = 0; t < 16; t++) {
            mx0 = fmaxf(mx0, fmaxf(s[t][0], s[t][1]));
            mx1 = fmaxf(mx1, fmaxf(s[t][2], s[t][3]));
        }
        mx0 = fmaxf(mx0, __shfl_xor_sync(0xffffffffu, mx0, 1));
        mx0 = fmaxf(mx0, __shfl_xor_sync(0xffffffffu, mx0, 2));
        mx1 = fmaxf(mx1, __shfl_xor_sync(0xffffffffu, mx1, 1));
        mx1 = fmaxf(mx1, __shfl_xor_sync(0xffffffffu, mx1, 2));
        float mn0 = fmaxf(mc0, mx0), mn1 = fmaxf(mc1, mx1);
        float sc0 = __expf(mc0 - mn0), sc1 = __expf(mc1 - mn1);
        mc0 = mn0; mc1 = mn1;

        float rs0 = 0.f, rs1 = 0.f;
#pragma unroll
        for (int t = 0; t < 16; t++) {
            float p0 = __expf(s[t][0] - mn0);
            float p1 = __expf(s[t][1] - mn0);
            float p2 = __expf(s[t][2] - mn1);
            float p3 = __expf(s[t][3] - mn1);
            rs0 += p0 + p1; rs1 += p2 + p3;
            s[t][0] = p0; s[t][1] = p1; s[t][2] = p2; s[t][3] = p3;
        }
        rs0 += __shfl_xor_sync(0xffffffffu, rs0, 1);
        rs0 += __shfl_xor_sync(0xffffffffu, rs0, 2);
        rs1 += __shfl_xor_sync(0xffffffffu, rs1, 1);
        rs1 += __shfl_xor_sync(0xffffffffu, rs1, 2);
        lc0 = lc0 * sc0 + rs0;
        lc1 = lc1 * sc1 + rs1;

        // ---- pack P into A-fragments (C-layout == A-layout identity) ----
        uint32_t ph[8][4], pl[8][4];
#pragma unroll
        for (int kt = 0; kt < 8; kt++) {
            split2(s[2 * kt][0],     s[2 * kt][1],     ph[kt][0], pl[kt][0]);
            split2(s[2 * kt][2],     s[2 * kt][3],     ph[kt][1], pl[kt][1]);
            split2(s[2 * kt + 1][0], s[2 * kt + 1][1], ph[kt][2], pl[kt][2]);
            split2(s[2 * kt + 1][2], s[2 * kt + 1][3], ph[kt][3], pl[kt][3]);
        }

        // ---- rescale O, then GEMM2: O += Ph*Xh + Ph*Xl + Pl*Xh ----
#pragma unroll
        for (int t = 0; t < 8; t++) {
            o[t][0] *= sc0; o[t][1] *= sc0;
            o[t][2] *= sc1; o[t][3] *= sc1;
        }
        {
            int g = lane >> 3, rr = lane & 7;
#pragma unroll
            for (int np = 0; np < 4; np++) {
                int brow = np * 16 + ((g >> 1) << 3) + rr;
#pragma unroll
                for (int kt = 0; kt < 8; kt++) {
                    uint32_t off = swz16(brow, kt * 2 + (g & 1));
                    uint32_t x0, x1, x2, x3, y0, y1, y2, y3;
                    ldsm4(x0, x1, x2, x3, sb + OFF_XH + off);
                    ldsm4(y0, y1, y2, y3, sb + OFF_XL + off);
                    mma16816(o[2 * np],     ph[kt], x0, x1);
                    mma16816(o[2 * np + 1], ph[kt], x2, x3);
                    mma16816(o[2 * np],     ph[kt], y0, y1);
                    mma16816(o[2 * np + 1], ph[kt], y2, y3);
                    mma16816(o[2 * np],     pl[kt], x0, x1);
                    mma16816(o[2 * np + 1], pl[kt], x2, x3);
                }
            }
        }
    }

    // ---- epilogue: write unnormalized partials + m, l ----
    {
        int q = lane >> 2;
        int cb = (lane & 3) * 2;
        int r_lo = row0 + m0 + q;
        int r_hi = r_lo + 8;
        float* olo = g_Opart[half] + (size_t)r_lo * DIM;
        float* ohi = g_Opart[half] + (size_t)r_hi * DIM;
#pragma unroll
        for (int t = 0; t < 8; t++) {
            olo[t * 8 + cb]     = o[t][0];
            olo[t * 8 + cb + 1] = o[t][1];
            ohi[t * 8 + cb]     = o[t][2];
            ohi[t * 8 + cb + 1] = o[t][3];
        }
        if ((lane & 3) == 0) {
            g_mpart[half][r_lo] = mc0; g_mpart[half][r_hi] = mc1;
            g_lpart[half][r_lo] = lc0; g_lpart[half][r_hi] = lc1;
        }
    }
}

// ---------------- combine the two KV halves ----------------
__global__ __launch_bounds__(64) void combine_kernel(float* __restrict__ out) {
    int row = blockIdx.x;
    int c = threadIdx.x;
    float m0 = g_mpart[0][row], m1 = g_mpart[1][row];
    float M = fmaxf(m0, m1);
    float w0 = __expf(m0 - M), w1 = __expf(m1 - M);
    float inv = 1.0f / (g_lpart[0][row] * w0 + g_lpart[1][row] * w1);
    out[(size_t)row * DIM + c] =
        (g_Opart[0][(size_t)row * DIM + c] * w0 + g_Opart[1][(size_t)row * DIM + c] * w1) * inv;
}

extern "C" void kernel_launch(void* const* d_in, const int* in_sizes, int n_in,
                              void* d_out, int out_size) {
    const float* x = (const float*)d_in[0];
    const float* R = (const float*)d_in[1];
    const float* E = (const float*)d_in[2];
    float* out = (float*)d_out;

    proj_kernel<<<N_TOK / 4, 256>>>(x, R, E);

    cudaFuncSetAttribute(attn_kernel, cudaFuncAttributeMaxDynamicSharedMemorySize, SMEM_TOTAL);
    attn_kernel<<<(N_TOK / BM) * 2, 256, SMEM_TOTAL>>>();

    combine_kernel<<<N_TOK, 64>>>(out);
}

// round 5
// speedup vs baseline: 3.5066x; 1.1976x over previous
#include <cuda_runtime.h>
#include <cuda_bf16.h>
#include <cstdint>

#define N_TOK 8192
#define DIM   64
#define BM    64
#define BN    128
#define HALF_KV 4096
#define NITER (HALF_KV / BN)   // 32

// ---------------- global scratch ----------------
__device__ __nv_bfloat16 g_Qh[N_TOK * DIM], g_Ql[N_TOK * DIM];
__device__ __nv_bfloat16 g_Kh[N_TOK * DIM], g_Kl[N_TOK * DIM];
__device__ __nv_bfloat16 g_Xth[DIM * N_TOK], g_Xtl[DIM * N_TOK];
__device__ float g_Opart[2][N_TOK * DIM];
__device__ float g_mpart[2][N_TOK];
__device__ float g_lpart[2][N_TOK];

// ---------------- helpers ----------------
__device__ __forceinline__ uint32_t smem_u32(const void* p) {
    uint32_t a;
    asm("{ .reg .u64 t; cvta.to.shared.u64 t, %1; cvt.u32.u64 %0, t; }" : "=r"(a) : "l"(p));
    return a;
}
__device__ __forceinline__ uint32_t swz8(uint32_t row, uint32_t ch) {
    return row * 128u + ((ch ^ (row & 7u)) << 4);
}
__device__ __forceinline__ uint32_t swz16(uint32_t row, uint32_t ch) {
    return row * 256u + ((ch ^ (row & 7u)) << 4);
}
__device__ __forceinline__ void ldsm4(uint32_t& r0, uint32_t& r1, uint32_t& r2,
                                      uint32_t& r3, uint32_t addr) {
    asm volatile("ldmatrix.sync.aligned.m8n8.x4.shared.b16 {%0,%1,%2,%3}, [%4];"
                 : "=r"(r0), "=r"(r1), "=r"(r2), "=r"(r3) : "r"(addr));
}
__device__ __forceinline__ void mma16816(float* c, const uint32_t* a, uint32_t b0,
                                         uint32_t b1) {
    asm volatile(
        "mma.sync.aligned.m16n8k16.row.col.f32.bf16.bf16.f32 "
        "{%0,%1,%2,%3}, {%4,%5,%6,%7}, {%8,%9}, {%0,%1,%2,%3};"
        : "+f"(c[0]), "+f"(c[1]), "+f"(c[2]), "+f"(c[3])
        : "r"(a[0]), "r"(a[1]), "r"(a[2]), "r"(a[3]), "r"(b0), "r"(b1));
}
__device__ __forceinline__ uint32_t pk2bf(float a, float b) {
    __nv_bfloat16 ha = __float2bfloat16(a), hb = __float2bfloat16(b);
    return ((uint32_t)__bfloat16_as_ushort(hb) << 16) | (uint32_t)__bfloat16_as_ushort(ha);
}
__device__ __forceinline__ void split2(float a, float b, uint32_t& hi, uint32_t& lo) {
    __nv_bfloat16 ha = __float2bfloat16(a), hb = __float2bfloat16(b);
    hi = ((uint32_t)__bfloat16_as_ushort(hb) << 16) | (uint32_t)__bfloat16_as_ushort(ha);
    lo = pk2bf(a - __bfloat162float(ha), b - __bfloat162float(hb));
}
__device__ __forceinline__ void cpa16(uint32_t dst, const void* src) {
    asm volatile("cp.async.cg.shared.global [%0], [%1], 16;" :: "r"(dst), "l"(src));
}
#define CP_COMMIT() asm volatile("cp.async.commit_group;" ::: "memory")
#define CP_WAIT(n)  asm volatile("cp.async.wait_group %0;" :: "n"(n) : "memory")

// ---------------- projection + split kernel ----------------
// 128 blocks x 64 rows; R/E loaded once per block; Xt stores coalesced via smem
__global__ __launch_bounds__(256) void proj_kernel(const float* __restrict__ x,
                                                   const float* __restrict__ R,
                                                   const float* __restrict__ E) {
    extern __shared__ float psm[];
    float* Rs = psm;                 // 4096
    float* Es = psm + 4096;          // 4096
    float* xs = psm + 8192;          // 64*65 padded
    int tid = threadIdx.x;
    int row0 = blockIdx.x * 64;
    {
        const float4* Rsrc = (const float4*)R;
        const float4* Esrc = (const float4*)E;
        float4* Rd = (float4*)Rs;
        float4* Ed = (float4*)Es;
#pragma unroll
        for (int i = tid; i < 1024; i += 256) { Rd[i] = Rsrc[i]; Ed[i] = Esrc[i]; }
    }
    // stage x tile (padded)
#pragma unroll
    for (int i = tid; i < 4096; i += 256) {
        int row = i >> 6, c = i & 63;
        xs[row * 65 + c] = x[(size_t)(row0 + row) * 64 + c];
    }
    __syncthreads();

    // coalesced transposed split-store of x
#pragma unroll
    for (int i = tid; i < 4096; i += 256) {
        int d = i >> 6, row = i & 63;
        float xv = xs[row * 65 + d];
        __nv_bfloat16 xh = __float2bfloat16(xv);
        g_Xth[(size_t)d * N_TOK + row0 + row] = xh;
        g_Xtl[(size_t)d * N_TOK + row0 + row] =
            __float2bfloat16(xv - __bfloat162float(xh));
    }

    // each thread: 16 rows x 1 col
    int ty = tid >> 6, col = tid & 63;
    float aq[16], ak[16];
#pragma unroll
    for (int r = 0; r < 16; r++) { aq[r] = 0.f; ak[r] = 0.f; }
#pragma unroll 8
    for (int k = 0; k < 64; k++) {
        float rv = Rs[k * 64 + col];
        float ev = Es[k * 64 + col];
#pragma unroll
        for (int r = 0; r < 16; r++) {
            float xv = xs[(r * 4 + ty) * 65 + k];
            aq[r] = fmaf(xv, rv, aq[r]);
            ak[r] = fmaf(xv, ev, ak[r]);
        }
    }
#pragma unroll
    for (int r = 0; r < 16; r++) {
        int row = row0 + r * 4 + ty;
        float q = aq[r] * 0.125f;
        __nv_bfloat16 qh = __float2bfloat16(q);
        g_Qh[(size_t)row * 64 + col] = qh;
        g_Ql[(size_t)row * 64 + col] = __float2bfloat16(q - __bfloat162float(qh));
        __nv_bfloat16 kh = __float2bfloat16(ak[r]);
        g_Kh[(size_t)row * 64 + col] = kh;
        g_Kl[(size_t)row * 64 + col] = __float2bfloat16(ak[r] - __bfloat162float(kh));
    }
}
#define PROJ_SMEM ((4096 + 4096 + 64 * 65) * 4)

// ---------------- fused flash attention (mma.sync HMMA, 2 CTA/SM) ----------------
#define OFF_KH 0
#define OFF_KL 16384
#define OFF_XH 32768
#define OFF_XL 49152
#define SMEM_TOTAL 65536

__global__ __launch_bounds__(128, 2) void attn_kernel() {
    extern __shared__ char sm[];
    uint32_t sb = smem_u32(sm);
    const int tid = threadIdx.x;
    const int lane = tid & 31;
    const int w = tid >> 5;
    const int m0 = w * 16;
    const int rb = blockIdx.x >> 1;
    const int half = blockIdx.x & 1;
    const int row0 = rb * BM;

    // ---- stage Q (hi/lo) into K smem region, build A-fragments once ----
#pragma unroll
    for (int i = tid; i < 64 * 8; i += 128) {
        int row = i >> 3, ch = i & 7;
        uint32_t sw = swz8(row, ch);
        *(uint4*)(sm + OFF_KH + sw) = *(const uint4*)(g_Qh + (size_t)(row0 + row) * DIM + ch * 8);
        *(uint4*)(sm + OFF_KL + sw) = *(const uint4*)(g_Ql + (size_t)(row0 + row) * DIM + ch * 8);
    }
    __syncthreads();

    uint32_t qh[4][4], ql[4][4];
    {
        int g = lane >> 3, rr = lane & 7;
        int arow = m0 + ((g & 1) << 3) + rr;
#pragma unroll
        for (int ks = 0; ks < 4; ks++) {
            uint32_t off = swz8(arow, ks * 2 + (g >> 1));
            ldsm4(qh[ks][0], qh[ks][1], qh[ks][2], qh[ks][3], sb + OFF_KH + off);
            ldsm4(ql[ks][0], ql[ks][1], ql[ks][2], ql[ks][3], sb + OFF_KL + off);
        }
    }

    float o[8][4];
#pragma unroll
    for (int t = 0; t < 8; t++)
#pragma unroll
        for (int j = 0; j < 4; j++) o[t][j] = 0.f;
    float mc0 = -3.0e38f, mc1 = -3.0e38f, lc0 = 0.f, lc1 = 0.f;

    for (int it = 0; it < NITER; it++) {
        __syncthreads();   // previous tiles fully consumed
        int jb = half * HALF_KV + it * BN;
        // ---- cp.async K tile (group 0) ----
#pragma unroll
        for (int i = tid; i < 128 * 8; i += 128) {
            int row = i >> 3, ch = i & 7;
            uint32_t sw = swz8(row, ch);
            cpa16(sb + OFF_KH + sw, g_Kh + (size_t)(jb + row) * DIM + ch * 8);
            cpa16(sb + OFF_KL + sw, g_Kl + (size_t)(jb + row) * DIM + ch * 8);
        }
        CP_COMMIT();
        // ---- cp.async X tile (group 1), lands during GEMM1/softmax ----
#pragma unroll
        for (int i = tid; i < 64 * 16; i += 128) {
            int row = i >> 4, ch = i & 15;
            uint32_t sw = swz16(row, ch);
            cpa16(sb + OFF_XH + sw, g_Xth + (size_t)row * N_TOK + jb + ch * 8);
            cpa16(sb + OFF_XL + sw, g_Xtl + (size_t)row * N_TOK + jb + ch * 8);
        }
        CP_COMMIT();
        CP_WAIT(1);        // K ready
        __syncthreads();

        // ---- GEMM1: S = Qh*Kh + Qh*Kl + Ql*Kh ----
        float s[16][4];
#pragma unroll
        for (int t = 0; t < 16; t++)
#pragma unroll
            for (int j = 0; j < 4; j++) s[t][j] = 0.f;
        {
            int g = lane >> 3, rr = lane & 7;
#pragma unroll
            for (int np = 0; np < 8; np++) {
                int brow = np * 16 + ((g >> 1) << 3) + rr;
#pragma unroll
                for (int ks = 0; ks < 4; ks++) {
                    uint32_t off = swz8(brow, ks * 2 + (g & 1));
                    uint32_t b0, b1, b2, b3, c0, c1, c2, c3;
                    ldsm4(b0, b1, b2, b3, sb + OFF_KH + off);
                    ldsm4(c0, c1, c2, c3, sb + OFF_KL + off);
                    mma16816(s[2 * np],     qh[ks], b0, b1);
                    mma16816(s[2 * np + 1], qh[ks], b2, b3);
                    mma16816(s[2 * np],     qh[ks], c0, c1);
                    mma16816(s[2 * np + 1], qh[ks], c2, c3);
                    mma16816(s[2 * np],     ql[ks], b0, b1);
                    mma16816(s[2 * np + 1], ql[ks], b2, b3);
                }
            }
        }

        // ---- online softmax on C-fragments ----
        float mx0 = -3.0e38f, mx1 = -3.0e38f;
#pragma unroll
        for (int t = 0; t < 16; t++) {
            mx0 = fmaxf(mx0, fmaxf(s[t][0], s[t][1]));
            mx1 = fmaxf(mx1, fmaxf(s[t][2], s[t][3]));
        }
        mx0 = fmaxf(mx0, __shfl_xor_sync(0xffffffffu, mx0, 1));
        mx0 = fmaxf(mx0, __shfl_xor_sync(0xffffffffu, mx0, 2));
        mx1 = fmaxf(mx1, __shfl_xor_sync(0xffffffffu, mx1, 1));
        mx1 = fmaxf(mx1, __shfl_xor_sync(0xffffffffu, mx1, 2));
        float mn0 = fmaxf(mc0, mx0), mn1 = fmaxf(mc1, mx1);
        float sc0 = __expf(mc0 - mn0), sc1 = __expf(mc1 - mn1);
        mc0 = mn0; mc1 = mn1;

        float rs0 = 0.f, rs1 = 0.f;
#pragma unroll
        for (int t = 0; t < 16; t++) {
            float p0 = __expf(s[t][0] - mn0);
            float p1 = __expf(s[t][1] - mn0);
            float p2 = __expf(s[t][2] - mn1);
            float p3 = __expf(s[t][3] - mn1);
            rs0 += p0 + p1; rs1 += p2 + p3;
            s[t][0] = p0; s[t][1] = p1; s[t][2] = p2; s[t][3] = p3;
        }
        rs0 += __shfl_xor_sync(0xffffffffu, rs0, 1);
        rs0 += __shfl_xor_sync(0xffffffffu, rs0, 2);
        rs1 += __shfl_xor_sync(0xffffffffu, rs1, 1);
        rs1 += __shfl_xor_sync(0xffffffffu, rs1, 2);
        lc0 = lc0 * sc0 + rs0;
        lc1 = lc1 * sc1 + rs1;

        // ---- pack P into A-fragments ----
        uint32_t ph[8][4], pl[8][4];
#pragma unroll
        for (int kt = 0; kt < 8; kt++) {
            split2(s[2 * kt][0],     s[2 * kt][1],     ph[kt][0], pl[kt][0]);
            split2(s[2 * kt][2],     s[2 * kt][3],     ph[kt][1], pl[kt][1]);
            split2(s[2 * kt + 1][0], s[2 * kt + 1][1], ph[kt][2], pl[kt][2]);
            split2(s[2 * kt + 1][2], s[2 * kt + 1][3], ph[kt][3], pl[kt][3]);
        }

        // ---- rescale O ----
#pragma unroll
        for (int t = 0; t < 8; t++) {
            o[t][0] *= sc0; o[t][1] *= sc0;
            o[t][2] *= sc1; o[t][3] *= sc1;
        }
        CP_WAIT(0);        // X ready
        __syncthreads();

        // ---- GEMM2: O += Ph*Xh + Ph*Xl + Pl*Xh ----
        {
            int g = lane >> 3, rr = lane & 7;
#pragma unroll
            for (int np = 0; np < 4; np++) {
                int brow = np * 16 + ((g >> 1) << 3) + rr;
#pragma unroll
                for (int kt = 0; kt < 8; kt++) {
                    uint32_t off = swz16(brow, kt * 2 + (g & 1));
                    uint32_t x0, x1, x2, x3, y0, y1, y2, y3;
                    ldsm4(x0, x1, x2, x3, sb + OFF_XH + off);
                    ldsm4(y0, y1, y2, y3, sb + OFF_XL + off);
                    mma16816(o[2 * np],     ph[kt], x0, x1);
                    mma16816(o[2 * np + 1], ph[kt], x2, x3);
                    mma16816(o[2 * np],     ph[kt], y0, y1);
                    mma16816(o[2 * np + 1], ph[kt], y2, y3);
                    mma16816(o[2 * np],     pl[kt], x0, x1);
                    mma16816(o[2 * np + 1], pl[kt], x2, x3);
                }
            }
        }
    }

    // ---- epilogue ----
    {
        int q = lane >> 2;
        int cb = (lane & 3) * 2;
        int r_lo = row0 + m0 + q;
        int r_hi = r_lo + 8;
        float* olo = g_Opart[half] + (size_t)r_lo * DIM;
        float* ohi = g_Opart[half] + (size_t)r_hi * DIM;
#pragma unroll
        for (int t = 0; t < 8; t++) {
            olo[t * 8 + cb]     = o[t][0];
            olo[t * 8 + cb + 1] = o[t][1];
            ohi[t * 8 + cb]     = o[t][2];
            ohi[t * 8 + cb + 1] = o[t][3];
        }
        if ((lane & 3) == 0) {
            g_mpart[half][r_lo] = mc0; g_mpart[half][r_hi] = mc1;
            g_lpart[half][r_lo] = lc0; g_lpart[half][r_hi] = lc1;
        }
    }
}

// ---------------- combine ----------------
__global__ __launch_bounds__(256) void combine_kernel(float* __restrict__ out) {
    int idx = blockIdx.x * 256 + threadIdx.x;
    int row = idx >> 6;
    int c = idx & 63;
    float m0 = g_mpart[0][row], m1 = g_mpart[1][row];
    float M = fmaxf(m0, m1);
    float w0 = __expf(m0 - M), w1 = __expf(m1 - M);
    float inv = 1.0f / (g_lpart[0][row] * w0 + g_lpart[1][row] * w1);
    out[(size_t)row * DIM + c] =
        (g_Opart[0][(size_t)row * DIM + c] * w0 + g_Opart[1][(size_t)row * DIM + c] * w1) * inv;
}

extern "C" void kernel_launch(void* const* d_in, const int* in_sizes, int n_in,
                              void* d_out, int out_size) {
    const float* x = (const float*)d_in[0];
    const float* R = (const float*)d_in[1];
    const float* E = (const float*)d_in[2];
    float* out = (float*)d_out;

    cudaFuncSetAttribute(proj_kernel, cudaFuncAttributeMaxDynamicSharedMemorySize, PROJ_SMEM);
    proj_kernel<<<N_TOK / 64, 256, PROJ_SMEM>>>(x, R, E);

    cudaFuncSetAttribute(attn_kernel, cudaFuncAttributeMaxDynamicSharedMemorySize, SMEM_TOTAL);
    attn_kernel<<<(N_TOK / BM) * 2, 128, SMEM_TOTAL>>>();

    combine_kernel<<<(N_TOK * DIM) / 256, 256>>>(out);
}